// round 14
// baseline (speedup 1.0000x reference)
#include <cuda_runtime.h>
#include <math.h>

#define NN   2048
#define CC   64
#define NT   128            // threads per block
#define JPT  4              // j's per thread
#define JB   (NT * JPT)     // 512 j columns per block
#define GX   (NN / JB)      // 4
#define ICH  8              // i rows per block
#define GY   (NN / ICH)     // 256
#define NBLK (GX * GY)      // 1024
#define NBUCK 64
#define L2E  1.4426950408889634f

// ---- device scratch (zero-init at load; counters reset by last block) ----
__device__ float4   g_pos[NN];   // x, y, z, |p|^2
__device__ float4   g_jn[NN];    // eR_lo, eD_lo, -s0, sqrt(w0)   (j-side)
__device__ float4   g_in[NN];    // eR_hi, eD_hi, -s0, sqrt(w0)   (i-side)
__device__ double   g_accs[NBUCK];
__device__ unsigned g_count;

__device__ __forceinline__ float sqrt_approx(float x) {
    float r; asm("sqrt.approx.f32 %0, %1;" : "=f"(r) : "f"(x)); return r;
}
__device__ __forceinline__ float rcp_approx(float x) {
    float r; asm("rcp.approx.f32 %0, %1;" : "=f"(r) : "f"(x)); return r;
}
__device__ __forceinline__ float ex2_approx(float x) {
    float r; asm("ex2.approx.f32 %0, %1;" : "=f"(r) : "f"(x)); return r;
}

// ---- per-node precompute, warp-cooperative: 1 warp per node ----
__global__ void __launch_bounds__(256) pre_kernel(
    const float* __restrict__ X,
    const float* __restrict__ embs,
    const float* __restrict__ w0,
    const float* __restrict__ s0,
    const float* __restrict__ df,
    const float* __restrict__ rf)
{
    const int lane = threadIdx.x & 31;
    const int n    = (blockIdx.x * 256 + threadIdx.x) >> 5;

    const float e0 = embs[(size_t)n * CC + lane];
    const float e1 = embs[(size_t)n * CC + 32 + lane];

    float rl = fmaf(e0, __ldg(rf + lane),      e1 * __ldg(rf + 32 + lane));
    float rh = fmaf(e0, __ldg(rf + 64 + lane), e1 * __ldg(rf + 96 + lane));
    float dl = fmaf(e0, __ldg(df + lane),      e1 * __ldg(df + 32 + lane));
    float dh = fmaf(e0, __ldg(df + 64 + lane), e1 * __ldg(df + 96 + lane));
#pragma unroll
    for (int off = 16; off > 0; off >>= 1) {
        rl += __shfl_xor_sync(0xFFFFFFFFu, rl, off);
        rh += __shfl_xor_sync(0xFFFFFFFFu, rh, off);
        dl += __shfl_xor_sync(0xFFFFFFFFu, dl, off);
        dh += __shfl_xor_sync(0xFFFFFFFFu, dh, off);
    }
    if (lane == 0) {
        const float x = X[3*n], y = X[3*n+1], z = X[3*n+2];
        const float q  = fmaf(x, x, fmaf(y, y, z * z));
        const float ns = -s0[n];
        const float sw = sqrtf(w0[n]);
        g_pos[n] = make_float4(x, y, z, q);
        g_jn[n]  = make_float4(ex2_approx(-L2E * rl), ex2_approx(-L2E * dl), ns, sw);
        g_in[n]  = make_float4(ex2_approx(-L2E * rh), ex2_approx(-L2E * dh), ns, sw);
    }
}

// ---- one pair evaluation (scalar, 5 MUFU: sqrt + rcp + 3 ex2) ----
__device__ __forceinline__ float pair_term(
    const float4 i1,   // -2xi, -2yi, -2zi, qi
    const float4 i2,   // eRhi, eDhi, -s0i, sw0i
    float xj, float yj, float zj, float qje,
    float eRj, float eDj, float ns0j, float swj)
{
    const float qsum = i1.w + qje;
    const float r2 = fmaf(i1.x, xj, fmaf(i1.y, yj, fmaf(i1.z, zj, qsum)));
    const float D  = sqrt_approx(r2);

    // both sigmoids from ONE rcp
    const float fR = fmaf(i2.x, eRj, 1.f);
    const float fD = fmaf(i2.y, eDj, 1.f);
    const float rp = rcp_approx(fR * fD);
    const float sr = rp * fD;
    const float sd = rp * fR;

    const float kf   = fmaf(0.8f, sr, 0.4f);
    const float nsum = i2.z + ns0j;
    const float Dm   = fmaf(nsum, kf, D);

    const float t    = ex2_approx((Dm * (-L2E)) * Dm);
    const float u    = ex2_approx(fmaf(0.6f * L2E, Dm, -0.09f * L2E));
    const float t2   = t * t;
    const float t3   = t2 * t;
    const float t4   = t2 * t2;
    const float t10  = (t4 * t4) * t2;
    const float attr3 = fmaf(t, u, t3 + t10);

    const float sd3n = fmaf(sd, -1.f/15.f, -1.f/30.f);
    const float wn   = (i2.w * swj) * sd3n;

    const float e = ex2_approx((D * (-0.3f * L2E)) * r2);

    return fmaf(wn, attr3, e);
}

// ---- pairwise energy: 4 j's per thread, 8 i's per block, single wave ----
__global__ void __launch_bounds__(NT, 7) pair_kernel(
    const float* __restrict__ mask, float* __restrict__ out)
{
    const int tid  = threadIdx.x;
    const int lane = tid & 31;
    const int wid  = tid >> 5;
    const int j0   = blockIdx.x * JB + tid * JPT;
    const int i0   = blockIdx.y * ICH;

    __shared__ float4 sI1[ICH];   // -2x, -2y, -2z, q
    __shared__ float4 sI2[ICH];   // eRhi, eDhi, -s0, sw0

    const float4* mrow = (const float4*)(mask + (size_t)i0 * NN + j0);

    // preload mask rows 0 and 1 (LDG.128 = 4 masks each)
    float4 mb0 = __ldg(mrow);
    float4 mb1 = __ldg(mrow + (NN / 4));

    // stage i-side data
    if (tid < ICH) {
        const float4 p = g_pos[i0 + tid];
        sI1[tid] = make_float4(-2.f * p.x, -2.f * p.y, -2.f * p.z, p.w);
        sI2[tid] = g_in[i0 + tid];
    }

    // j-side data (4 nodes)
    float xj[JPT], yj[JPT], zj[JPT], qje[JPT], eR[JPT], eD[JPT], ns[JPT], sw[JPT];
#pragma unroll
    for (int q = 0; q < JPT; q++) {
        const float4 p = g_pos[j0 + q];
        const float4 n = g_jn[j0 + q];
        xj[q] = p.x; yj[q] = p.y; zj[q] = p.z; qje[q] = p.w + 3e-6f;
        eR[q] = n.x; eD[q] = n.y; ns[q] = n.z; sw[q]  = n.w;
    }

    __syncthreads();

    float acc[JPT] = {0.f, 0.f, 0.f, 0.f};
#pragma unroll
    for (int k = 0; k < ICH; k++) {
        const float4 m = (k & 1) ? mb1 : mb0;
        // refill consumed buffer with row k+2 (prefetch distance 2)
        if (k + 2 < ICH) {
            if (k & 1) mb1 = __ldg(mrow + (k + 2) * (NN / 4));
            else       mb0 = __ldg(mrow + (k + 2) * (NN / 4));
        }
        const float4 i1 = sI1[k];
        const float4 i2 = sI2[k];
        const float mm[JPT] = {m.x, m.y, m.z, m.w};
#pragma unroll
        for (int q = 0; q < JPT; q++) {
            const float tq = pair_term(i1, i2, xj[q], yj[q], zj[q], qje[q],
                                       eR[q], eD[q], ns[q], sw[q]);
            acc[q] = fmaf(mm[q], tq, acc[q]);
        }
    }

    float a = 5.f * ((acc[0] + acc[1]) + (acc[2] + acc[3]));

    // ---- warp reduction + per-warp bucket atomic ----
#pragma unroll
    for (int off = 16; off > 0; off >>= 1)
        a += __shfl_down_sync(0xFFFFFFFFu, a, off);

    if (lane == 0) {
        const int bucket = ((blockIdx.y * GX + blockIdx.x) * 4 + wid) & (NBUCK - 1);
        atomicAdd(&g_accs[bucket], (double)a);
    }
    __syncthreads();

    if (tid == 0) {
        __threadfence();
        const unsigned prev = atomicAdd(&g_count, 1u);
        if (prev == NBLK - 1) {
            __threadfence();
            double total = 0.0;
#pragma unroll
            for (int b = 0; b < NBUCK; b++) {
                total += g_accs[b];
                g_accs[b] = 0.0;     // reset for next graph replay
            }
            const float r = (float)total;
            out[0] = isnan(r) ? 1e-6f : r;
            g_count = 0u;
        }
    }
}

extern "C" void kernel_launch(void* const* d_in, const int* in_sizes, int n_in,
                              void* d_out, int out_size) {
    const float* X    = (const float*)d_in[0];
    const float* embs = (const float*)d_in[1];
    const float* w0   = (const float*)d_in[2];
    const float* s0   = (const float*)d_in[3];
    const float* mask = (const float*)d_in[4];
    const float* df   = (const float*)d_in[5];
    const float* rf   = (const float*)d_in[6];
    float* out = (float*)d_out;

    pre_kernel<<<NN / 8, 256>>>(X, embs, w0, s0, df, rf);
    dim3 grid(GX, GY);   // 4 x 256 = 1024 blocks of 128 threads, 7/SM single wave
    pair_kernel<<<grid, NT>>>(mask, out);
}

// round 15
// speedup vs baseline: 1.1083x; 1.1083x over previous
#include <cuda_runtime.h>
#include <math.h>

#define NN   2048
#define CC   64
#define NT   128            // threads per block
#define JPT  2              // j's per thread (independent scalar chains)
#define JB   (NT * JPT)     // 256 j columns per block
#define GX   (NN / JB)      // 8
#define ICH  8              // i rows per block
#define GY   (NN / ICH)     // 256
#define NBLK (GX * GY)      // 2048
#define NBUCK 64
#define L2E  1.4426950408889634f

// ---- device scratch (zero-init at load; counters reset by last block) ----
__device__ float4   g_pos[NN];   // x, y, z, |p|^2
__device__ float4   g_jn[NN];    // eR_lo, eD_lo, -s0, sqrt(w0)   (j-side)
__device__ float4   g_in[NN];    // eR_hi, eD_hi, -s0, sqrt(w0)   (i-side)
__device__ double   g_accs[NBUCK];
__device__ unsigned g_count;

__device__ __forceinline__ float sqrt_approx(float x) {
    float r; asm("sqrt.approx.f32 %0, %1;" : "=f"(r) : "f"(x)); return r;
}
__device__ __forceinline__ float rcp_approx(float x) {
    float r; asm("rcp.approx.f32 %0, %1;" : "=f"(r) : "f"(x)); return r;
}
__device__ __forceinline__ float ex2_approx(float x) {
    float r; asm("ex2.approx.f32 %0, %1;" : "=f"(r) : "f"(x)); return r;
}

// ---- per-node precompute, warp-cooperative: 1 warp per node ----
__global__ void __launch_bounds__(256) pre_kernel(
    const float* __restrict__ X,
    const float* __restrict__ embs,
    const float* __restrict__ w0,
    const float* __restrict__ s0,
    const float* __restrict__ df,
    const float* __restrict__ rf)
{
    const int lane = threadIdx.x & 31;
    const int n    = (blockIdx.x * 256 + threadIdx.x) >> 5;

    const float e0 = embs[(size_t)n * CC + lane];
    const float e1 = embs[(size_t)n * CC + 32 + lane];

    float rl = fmaf(e0, __ldg(rf + lane),      e1 * __ldg(rf + 32 + lane));
    float rh = fmaf(e0, __ldg(rf + 64 + lane), e1 * __ldg(rf + 96 + lane));
    float dl = fmaf(e0, __ldg(df + lane),      e1 * __ldg(df + 32 + lane));
    float dh = fmaf(e0, __ldg(df + 64 + lane), e1 * __ldg(df + 96 + lane));
#pragma unroll
    for (int off = 16; off > 0; off >>= 1) {
        rl += __shfl_xor_sync(0xFFFFFFFFu, rl, off);
        rh += __shfl_xor_sync(0xFFFFFFFFu, rh, off);
        dl += __shfl_xor_sync(0xFFFFFFFFu, dl, off);
        dh += __shfl_xor_sync(0xFFFFFFFFu, dh, off);
    }
    if (lane == 0) {
        const float x = X[3*n], y = X[3*n+1], z = X[3*n+2];
        const float q  = fmaf(x, x, fmaf(y, y, z * z));
        const float ns = -s0[n];
        const float sw = sqrtf(w0[n]);
        g_pos[n] = make_float4(x, y, z, q);
        g_jn[n]  = make_float4(ex2_approx(-L2E * rl), ex2_approx(-L2E * dl), ns, sw);
        g_in[n]  = make_float4(ex2_approx(-L2E * rh), ex2_approx(-L2E * dh), ns, sw);
    }
    // signal dependents: all g_* writes above are visible after their wait
    asm volatile("griddepcontrol.launch_dependents;" ::: "memory");
}

// ---- one pair evaluation (scalar, 5 MUFU: sqrt + rcp + 3 ex2) ----
__device__ __forceinline__ float pair_term(
    const float4 i1,   // -2xi, -2yi, -2zi, qi
    const float4 i2,   // eRhi, eDhi, -s0i, sw0i
    float xj, float yj, float zj, float qje,
    float eRj, float eDj, float ns0j, float swj)
{
    const float qsum = i1.w + qje;
    const float r2 = fmaf(i1.x, xj, fmaf(i1.y, yj, fmaf(i1.z, zj, qsum)));
    const float D  = sqrt_approx(r2);

    // both sigmoids from ONE rcp: rp = 1/(fR*fD); sr = rp*fD; sd = rp*fR
    const float fR = fmaf(i2.x, eRj, 1.f);
    const float fD = fmaf(i2.y, eDj, 1.f);
    const float rp = rcp_approx(fR * fD);
    const float sr = rp * fD;
    const float sd = rp * fR;

    const float kf   = fmaf(0.8f, sr, 0.4f);
    const float nsum = i2.z + ns0j;
    const float Dm   = fmaf(nsum, kf, D);

    const float t    = ex2_approx((Dm * (-L2E)) * Dm);
    const float u    = ex2_approx(fmaf(0.6f * L2E, Dm, -0.09f * L2E));
    const float t2   = t * t;
    const float t3   = t2 * t;
    const float t4   = t2 * t2;
    const float t10  = (t4 * t4) * t2;
    const float attr3 = fmaf(t, u, t3 + t10);

    const float sd3n = fmaf(sd, -1.f/15.f, -1.f/30.f);
    const float wn   = (i2.w * swj) * sd3n;

    const float e = ex2_approx((D * (-0.3f * L2E)) * r2);

    return fmaf(wn, attr3, e);
}

// ---- pairwise energy: identical to R13 + PDL wait after mask prefetch ----
__global__ void __launch_bounds__(NT) pair_kernel(
    const float* __restrict__ mask, float* __restrict__ out)
{
    const int tid  = threadIdx.x;
    const int lane = tid & 31;
    const int wid  = tid >> 5;
    const int j0   = blockIdx.x * JB + tid * JPT;
    const int i0   = blockIdx.y * ICH;

    __shared__ float4 sI1[ICH];   // -2x, -2y, -2z, q
    __shared__ float4 sI2[ICH];   // eRhi, eDhi, -s0, sw0

    const float2* mrow = (const float2*)(mask + (size_t)i0 * NN + j0);

    // mask prefetch is independent of pre_kernel — issue it BEFORE the PDL wait
    float2 mk0[4];
#pragma unroll
    for (int k = 0; k < 4; k++)
        mk0[k] = __ldg(mrow + k * (NN / 2));

    // wait for pre_kernel's griddepcontrol.launch_dependents (g_* visible after)
    asm volatile("griddepcontrol.wait;" ::: "memory");

    // stage i-side data
    if (tid < ICH) {
        const float4 p = g_pos[i0 + tid];
        sI1[tid] = make_float4(-2.f * p.x, -2.f * p.y, -2.f * p.z, p.w);
        sI2[tid] = g_in[i0 + tid];
    }

    // j-side data (2 nodes)
    const float4 pA = g_pos[j0],  pB = g_pos[j0 + 1];
    const float4 nA = g_jn[j0],   nB = g_jn[j0 + 1];
    const float qAe = pA.w + 3e-6f, qBe = pB.w + 3e-6f;

    __syncthreads();

    // issue group 1 loads before computing group 0
    float2 mk1[4];
#pragma unroll
    for (int k = 0; k < 4; k++)
        mk1[k] = __ldg(mrow + (4 + k) * (NN / 2));

    float accA = 0.f, accB = 0.f;

    // ---- group 0 ----
#pragma unroll
    for (int k = 0; k < 4; k++) {
        const float4 i1 = sI1[k];
        const float4 i2 = sI2[k];
        const float tA = pair_term(i1, i2, pA.x, pA.y, pA.z, qAe,
                                   nA.x, nA.y, nA.z, nA.w);
        const float tB = pair_term(i1, i2, pB.x, pB.y, pB.z, qBe,
                                   nB.x, nB.y, nB.z, nB.w);
        accA = fmaf(mk0[k].x, tA, accA);
        accB = fmaf(mk0[k].y, tB, accB);
    }
    // ---- group 1 ----
#pragma unroll
    for (int k = 0; k < 4; k++) {
        const float4 i1 = sI1[4 + k];
        const float4 i2 = sI2[4 + k];
        const float tA = pair_term(i1, i2, pA.x, pA.y, pA.z, qAe,
                                   nA.x, nA.y, nA.z, nA.w);
        const float tB = pair_term(i1, i2, pB.x, pB.y, pB.z, qBe,
                                   nB.x, nB.y, nB.z, nB.w);
        accA = fmaf(mk1[k].x, tA, accA);
        accB = fmaf(mk1[k].y, tB, accB);
    }

    float acc = 5.f * (accA + accB);

    // ---- warp reduction + per-warp bucket atomic ----
#pragma unroll
    for (int off = 16; off > 0; off >>= 1)
        acc += __shfl_down_sync(0xFFFFFFFFu, acc, off);

    if (lane == 0) {
        const int bucket = ((blockIdx.y * GX + blockIdx.x) * 4 + wid) & (NBUCK - 1);
        atomicAdd(&g_accs[bucket], (double)acc);
    }
    __syncthreads();

    if (tid == 0) {
        __threadfence();
        const unsigned prev = atomicAdd(&g_count, 1u);
        if (prev == NBLK - 1) {
            __threadfence();
            double total = 0.0;
#pragma unroll
            for (int b = 0; b < NBUCK; b++) {
                total += g_accs[b];
                g_accs[b] = 0.0;     // reset for next graph replay
            }
            const float r = (float)total;
            out[0] = isnan(r) ? 1e-6f : r;
            g_count = 0u;
        }
    }
}

extern "C" void kernel_launch(void* const* d_in, const int* in_sizes, int n_in,
                              void* d_out, int out_size) {
    const float* X    = (const float*)d_in[0];
    const float* embs = (const float*)d_in[1];
    const float* w0   = (const float*)d_in[2];
    const float* s0   = (const float*)d_in[3];
    const float* mask = (const float*)d_in[4];
    const float* df   = (const float*)d_in[5];
    const float* rf   = (const float*)d_in[6];
    float* out = (float*)d_out;

    pre_kernel<<<NN / 8, 256>>>(X, embs, w0, s0, df, rf);

    // PDL: pair_kernel may launch while pre_kernel is still running;
    // its griddepcontrol.wait gates on pre_kernel's launch_dependents.
    cudaLaunchConfig_t cfg = {};
    cfg.gridDim  = dim3(GX, GY);    // 8 x 256 = 2048 blocks of 128 threads
    cfg.blockDim = dim3(NT, 1, 1);
    cudaLaunchAttribute at[1];
    at[0].id = cudaLaunchAttributeProgrammaticStreamSerialization;
    at[0].val.programmaticStreamSerializationAllowed = 1;
    cfg.attrs    = at;
    cfg.numAttrs = 1;
    cudaLaunchKernelEx(&cfg, pair_kernel, mask, out);
}